// round 17
// baseline (speedup 1.0000x reference)
#include <cuda_runtime.h>
#include <cstdint>

// EConv: out[dst] += x[src] * edge_attr[e]  over 1M edges, d=64
// Champion schedule (edge-order, EPT=4 front-batched, red.global.add.v4.f32,
// 32-bit byte offsets, block=256) run as a PERSISTENT single-wave grid
// (148 SMs x 7 blocks) with grid-stride over edge-groups to remove
// inter-wave transition overhead.
// d_in[0]: x          float32 [100000*64]
// d_in[1]: edge_index int32   [2*1000000]  (row 0 = dst, row 1 = src)
// d_in[2]: edge_attr  float32 [1000000*64]
// d_out:   float32 [100000*64]

#define ROW_BYTES 256u   // 64 floats
#define EPT 4            // edges per thread
#define NSM 148
#define BLOCKS_PER_SM 7
#define NBLK (NSM * BLOCKS_PER_SM)   // 1036 blocks = one wave

__global__ __launch_bounds__(256) void econv_kernel(
    const char* __restrict__ x_b,         // x base (bytes)
    const int* __restrict__ dst_idx,      // [E]
    const int* __restrict__ src_idx,      // [E]
    const char* __restrict__ attr_b,      // edge_attr base (bytes)
    char* __restrict__ out_b,             // out base (bytes)
    int E)
{
    unsigned cb = (threadIdx.x & 15) * 16u;  // this thread's float4 chunk (bytes)
    int lane_g = (blockIdx.x * blockDim.x + threadIdx.x) >> 4;  // first group
    const int n_groups = E / EPT;                    // 250000
    const int stride_g = (NBLK * 256) >> 4;          // groups per wave step

    for (int g = lane_g; g < n_groups; g += stride_g) {
        int e0 = g * EPT;

        // One LDG.128 each for 4 src + 4 dst indices (e0 is 4-aligned)
        int4 s4 = __ldcs((const int4*)(src_idx + e0));
        int4 d4 = __ldcs((const int4*)(dst_idx + e0));
        int src[EPT] = {s4.x, s4.y, s4.z, s4.w};
        int dst[EPT] = {d4.x, d4.y, d4.z, d4.w};

        // Front-batch the 8 data loads (32-bit offsets).
        // x: default caching (L2-resident). attr: evict-first stream.
        float4 xv[EPT], av[EPT];
        unsigned ab = (unsigned)e0 * ROW_BYTES + cb;
#pragma unroll
        for (int i = 0; i < EPT; i++) {
            xv[i] = __ldg((const float4*)(x_b + ((unsigned)src[i] * ROW_BYTES + cb)));
            av[i] = __ldcs((const float4*)(attr_b + ab + (unsigned)i * ROW_BYTES));
        }

#pragma unroll
        for (int i = 0; i < EPT; i++) {
            av[i].x *= xv[i].x;
            av[i].y *= xv[i].y;
            av[i].z *= xv[i].z;
            av[i].w *= xv[i].w;
            char* p = out_b + ((unsigned)dst[i] * ROW_BYTES + cb);
            asm volatile(
                "red.global.add.v4.f32 [%0], {%1, %2, %3, %4};"
                :: "l"(p), "f"(av[i].x), "f"(av[i].y), "f"(av[i].z), "f"(av[i].w)
                : "memory");
        }
    }
}

extern "C" void kernel_launch(void* const* d_in, const int* in_sizes, int n_in,
                              void* d_out, int out_size) {
    const char* x_b = (const char*)d_in[0];
    const int* edge_index = (const int*)d_in[1];
    const char* attr_b = (const char*)d_in[2];

    int E = in_sizes[1] / 2;                 // 1,000,000
    const int* dst_idx = edge_index;         // row 0
    const int* src_idx = edge_index + E;     // row 1

    // Zero the output (graph-capturable memset node; required every replay)
    cudaMemsetAsync(d_out, 0, (size_t)out_size * sizeof(float));

    econv_kernel<<<NBLK, 256>>>(
        x_b, dst_idx, src_idx, attr_b, (char*)d_out, E);
}